// round 1
// baseline (speedup 1.0000x reference)
#include <cuda_runtime.h>

// MedianPool2d 3x3, stride 1, reflect pad (1,1,1,1)
// Input:  float32 [16, 3, 512, 512]  (48 planes of 512x512)
// Output: float32 [16, 3, 512, 512]
//
// One block of 128 threads per (plane, output row). Each thread computes 4
// contiguous outputs along W using the separable column-sort median trick:
//   - sort each of the 6 needed 3-tall columns (lo/mid/hi), 6 FMNMX each
//   - median = med3( max(lo0,lo1,lo2), med3(mid0,mid1,mid2), min(hi0,hi1,hi2) )
// => 84 FMNMX per thread for 4 outputs (21/output), vs 19-25 for naive.

#define W 512
#define H 512

__device__ __forceinline__ float med3(float a, float b, float c) {
    // median of 3 = max(min(a,b), min(max(a,b), c))
    return fmaxf(fminf(a, b), fminf(fmaxf(a, b), c));
}

__device__ __forceinline__ void sort3(float a, float b, float c,
                                      float& lo, float& mi, float& hi) {
    float x0 = fminf(a, b);
    float x1 = fmaxf(a, b);
    lo = fminf(x0, c);
    float t = fmaxf(x0, c);
    mi = fminf(x1, t);
    hi = fmaxf(x1, t);
}

__global__ __launch_bounds__(128, 8)
void median3x3_kernel(const float* __restrict__ x, float* __restrict__ out) {
    const int h     = blockIdx.x;        // output row 0..511
    const int plane = blockIdx.y;        // 0..47 (B*C)
    const int tid   = threadIdx.x;       // 0..127
    const int w0    = tid << 2;          // 4 outputs per thread

    const long base = (long)plane * (H * W);
    const float* p = x + base;

    // reflect rows
    const int hu = (h == 0)     ? 1       : h - 1;
    const int hd = (h == H - 1) ? H - 2   : h + 1;
    const float* r0 = p + (long)hu * W;
    const float* r1 = p + (long)h  * W;
    const float* r2 = p + (long)hd * W;

    // reflect columns for the two halo scalars
    const int wl = (w0 == 0)        ? 1     : w0 - 1;
    const int wr = (w0 + 4 == W)    ? W - 2 : w0 + 4;

    // load 3 rows x 6 columns: [wl, w0..w0+3, wr]
    float a[6], b[6], c[6];
    {
        float4 v = *reinterpret_cast<const float4*>(r0 + w0);
        a[0] = r0[wl]; a[1] = v.x; a[2] = v.y; a[3] = v.z; a[4] = v.w; a[5] = r0[wr];
    }
    {
        float4 v = *reinterpret_cast<const float4*>(r1 + w0);
        b[0] = r1[wl]; b[1] = v.x; b[2] = v.y; b[3] = v.z; b[4] = v.w; b[5] = r1[wr];
    }
    {
        float4 v = *reinterpret_cast<const float4*>(r2 + w0);
        c[0] = r2[wl]; c[1] = v.x; c[2] = v.y; c[3] = v.z; c[4] = v.w; c[5] = r2[wr];
    }

    // sort the 6 vertical columns once (shared across the 4 outputs)
    float lo[6], mi[6], hi[6];
#pragma unroll
    for (int j = 0; j < 6; j++) {
        sort3(a[j], b[j], c[j], lo[j], mi[j], hi[j]);
    }

    float4 res;
    float* rp = &res.x;
#pragma unroll
    for (int o = 0; o < 4; o++) {
        float mlo = fmaxf(fmaxf(lo[o], lo[o + 1]), lo[o + 2]);
        float mhi = fminf(fminf(hi[o], hi[o + 1]), hi[o + 2]);
        float mmi = med3(mi[o], mi[o + 1], mi[o + 2]);
        rp[o] = med3(mlo, mmi, mhi);
    }

    *reinterpret_cast<float4*>(out + base + (long)h * W + w0) = res;
}

extern "C" void kernel_launch(void* const* d_in, const int* in_sizes, int n_in,
                              void* d_out, int out_size) {
    const float* x = (const float*)d_in[0];
    float* out = (float*)d_out;
    dim3 grid(H, 48);   // 512 rows x (16*3) planes
    dim3 block(128);
    median3x3_kernel<<<grid, block>>>(x, out);
}

// round 2
// speedup vs baseline: 1.0865x; 1.0865x over previous
#include <cuda_runtime.h>

// MedianPool2d 3x3, stride 1, reflect pad (1,1,1,1)
// Input:  float32 [16, 3, 512, 512] -> Output same shape.
//
// Each thread computes a 4(W) x 4(H) output tile:
//  - loads 6 input rows x 6 columns (float4 + 2 reflected halo scalars per row)
//  - sorts row-pairs (1,2) and (3,4) once per column; each sorted pair serves
//    two vertical triples (sort3 given a sorted pair costs 4 ops)
//  - horizontal combines use sliding-window sharing:
//      max-of-3 lows / min-of-3 highs: shared middle pair (6 ops per 4 outputs)
//      med3 of mids: shared sorted pair (12 ops per 4 outputs)
//  - median9 = med3(max(lo), med(mi), min(hi))  [exact middle order statistic]
// => ~17.5 FMNMX/output (was 21) and ~2x less L1 traffic.

#define W 512
#define H 512

__device__ __forceinline__ float med3(float a, float b, float c) {
    return fmaxf(fminf(a, b), fminf(fmaxf(a, b), c));
}

__global__ __launch_bounds__(128, 6)
void median3x3_kernel(const float* __restrict__ x, float* __restrict__ out) {
    const int tid   = threadIdx.x;        // 0..127
    const int h0    = blockIdx.x << 2;    // 4 output rows per block-row
    const int plane = blockIdx.y;         // 0..47
    const int w0    = tid << 2;           // 4 outputs per thread along W

    const long base = (long)plane * (H * W);
    const float* p = x + base;

    const int wl = (w0 == 0)     ? 1     : w0 - 1;
    const int wr = (w0 + 4 == W) ? W - 2 : w0 + 4;

    // Load 6 rows (h0-1 .. h0+4, reflected) x 6 columns [wl, w0..w0+3, wr]
    float v[6][6];
#pragma unroll
    for (int r = 0; r < 6; r++) {
        int h = h0 - 1 + r;
        h = (h < 0) ? 1 : ((h >= H) ? H - 2 : h);
        const float* row = p + (long)h * W;
        float4 q = *reinterpret_cast<const float4*>(row + w0);
        v[r][0] = row[wl];
        v[r][1] = q.x; v[r][2] = q.y; v[r][3] = q.z; v[r][4] = q.w;
        v[r][5] = row[wr];
    }

    // Sorted row-pairs per column: (rows 1,2) and (rows 3,4)
    float p12l[6], p12h[6], p34l[6], p34h[6];
#pragma unroll
    for (int j = 0; j < 6; j++) {
        p12l[j] = fminf(v[1][j], v[2][j]);
        p12h[j] = fmaxf(v[1][j], v[2][j]);
        p34l[j] = fminf(v[3][j], v[4][j]);
        p34h[j] = fmaxf(v[3][j], v[4][j]);
    }

    // Output row r uses vertical triple:
    //   r=0: pair(1,2) + v0   r=1: pair(1,2) + v3
    //   r=2: pair(3,4) + v2   r=3: pair(3,4) + v5
#pragma unroll
    for (int r = 0; r < 4; r++) {
        const int third = (r == 0) ? 0 : (r == 1) ? 3 : (r == 2) ? 2 : 5;
        float lo[6], mi[6], hi[6];
#pragma unroll
        for (int j = 0; j < 6; j++) {
            float y0 = (r < 2) ? p12l[j] : p34l[j];
            float y1 = (r < 2) ? p12h[j] : p34h[j];
            float a  = v[third][j];
            float l  = fminf(y0, a);
            float t  = fmaxf(y0, a);
            lo[j] = l;
            mi[j] = fminf(y1, t);
            hi[j] = fmaxf(y1, t);
        }

        // max-of-3 lows, sliding with shared middle pair
        float sA = fmaxf(lo[1], lo[2]);
        float sB = fmaxf(lo[3], lo[4]);
        float mlo0 = fmaxf(lo[0], sA);
        float mlo1 = fmaxf(sA, lo[3]);
        float mlo2 = fmaxf(lo[2], sB);
        float mlo3 = fmaxf(sB, lo[5]);

        // min-of-3 highs
        float tA = fminf(hi[1], hi[2]);
        float tB = fminf(hi[3], hi[4]);
        float mhi0 = fminf(hi[0], tA);
        float mhi1 = fminf(tA, hi[3]);
        float mhi2 = fminf(hi[2], tB);
        float mhi3 = fminf(tB, hi[5]);

        // med3 of mids with shared sorted pair:
        //   med3(a, b, c) with (b,c) sorted to (q0,q1) = max(q0, min(q1, a))
        float q0A = fminf(mi[1], mi[2]), q1A = fmaxf(mi[1], mi[2]);
        float q0B = fminf(mi[3], mi[4]), q1B = fmaxf(mi[3], mi[4]);
        float mmi0 = fmaxf(q0A, fminf(q1A, mi[0]));
        float mmi1 = fmaxf(q0A, fminf(q1A, mi[3]));
        float mmi2 = fmaxf(q0B, fminf(q1B, mi[2]));
        float mmi3 = fmaxf(q0B, fminf(q1B, mi[5]));

        float4 res;
        res.x = med3(mlo0, mmi0, mhi0);
        res.y = med3(mlo1, mmi1, mhi1);
        res.z = med3(mlo2, mmi2, mhi2);
        res.w = med3(mlo3, mmi3, mhi3);

        *reinterpret_cast<float4*>(out + base + (long)(h0 + r) * W + w0) = res;
    }
}

extern "C" void kernel_launch(void* const* d_in, const int* in_sizes, int n_in,
                              void* d_out, int out_size) {
    const float* x = (const float*)d_in[0];
    float* out = (float*)d_out;
    dim3 grid(H / 4, 48);   // 128 row-tiles x 48 planes
    dim3 block(128);        // 128 threads x 4 cols = 512 wide
    median3x3_kernel<<<grid, block>>>(x, out);
}

// round 3
// speedup vs baseline: 1.1931x; 1.0980x over previous
#include <cuda_runtime.h>

// MedianPool2d 3x3, stride 1, reflect pad (1,1,1,1)
// float32 [16, 3, 512, 512] -> same shape.
//
// 4(W) x 4(H) outputs per thread, PHASED to cut register pressure:
//   frame rows f0..f5 = input rows h0-1 .. h0+4 (reflected)
//   pairA = sort(f1,f2) serves output rows 0 (third f0) and 1 (third f3)
//   pairB = sort(f3,f4) serves output rows 2 (third f2) and 3 (third f5)
// Load f0..f3 -> pairA (f1 dies) -> row0 (f0 dies) -> row1 -> load f4,f5
//   -> pairB (f4 dies) -> row2 (f2 dies) -> row3 (f5 dies)
// Horizontal combines use sliding-window pair sharing (as R2).
// ~17 FMNMX/output; goal this round: occupancy 50%->62.5% via 51-reg cap.

#define W 512
#define H 512

__device__ __forceinline__ float med3(float a, float b, float c) {
    return fmaxf(fminf(a, b), fminf(fmaxf(a, b), c));
}

struct Row6 { float v[6]; };

__device__ __forceinline__ Row6 load_row6(const float* __restrict__ row,
                                          int w0, int wl, int wr) {
    Row6 r;
    float4 q = *reinterpret_cast<const float4*>(row + w0);
    r.v[0] = row[wl];
    r.v[1] = q.x; r.v[2] = q.y; r.v[3] = q.z; r.v[4] = q.w;
    r.v[5] = row[wr];
    return r;
}

// Given sorted pair (pl <= ph) per column and a third row, compute the median
// over each of the 4 horizontal 3-wide windows, and store.
__device__ __forceinline__ void emit_row(const float* pl, const float* ph,
                                         const Row6& third,
                                         float* __restrict__ dst) {
    float lo[6], mi[6], hi[6];
#pragma unroll
    for (int j = 0; j < 6; j++) {
        float a = third.v[j];
        float l = fminf(pl[j], a);
        float t = fmaxf(pl[j], a);
        lo[j] = l;
        mi[j] = fminf(ph[j], t);
        hi[j] = fmaxf(ph[j], t);
    }

    // max-of-3 lows (shared middle pairs)
    float sA = fmaxf(lo[1], lo[2]);
    float sB = fmaxf(lo[3], lo[4]);
    float mlo0 = fmaxf(lo[0], sA);
    float mlo1 = fmaxf(sA, lo[3]);
    float mlo2 = fmaxf(lo[2], sB);
    float mlo3 = fmaxf(sB, lo[5]);

    // min-of-3 highs
    float tA = fminf(hi[1], hi[2]);
    float tB = fminf(hi[3], hi[4]);
    float mhi0 = fminf(hi[0], tA);
    float mhi1 = fminf(tA, hi[3]);
    float mhi2 = fminf(hi[2], tB);
    float mhi3 = fminf(tB, hi[5]);

    // med3 of mids (shared sorted pairs): med3(a | q0<=q1) = max(q0, min(q1, a))
    float q0A = fminf(mi[1], mi[2]), q1A = fmaxf(mi[1], mi[2]);
    float q0B = fminf(mi[3], mi[4]), q1B = fmaxf(mi[3], mi[4]);
    float mmi0 = fmaxf(q0A, fminf(q1A, mi[0]));
    float mmi1 = fmaxf(q0A, fminf(q1A, mi[3]));
    float mmi2 = fmaxf(q0B, fminf(q1B, mi[2]));
    float mmi3 = fmaxf(q0B, fminf(q1B, mi[5]));

    float4 res;
    res.x = med3(mlo0, mmi0, mhi0);
    res.y = med3(mlo1, mmi1, mhi1);
    res.z = med3(mlo2, mmi2, mhi2);
    res.w = med3(mlo3, mmi3, mhi3);
    *reinterpret_cast<float4*>(dst) = res;
}

__global__ __launch_bounds__(128, 10)
void median3x3_kernel(const float* __restrict__ x, float* __restrict__ out) {
    const int tid   = threadIdx.x;       // 0..127
    const int h0    = blockIdx.x << 2;   // 4 output rows per block
    const int plane = blockIdx.y;        // 0..47
    const int w0    = tid << 2;

    const long base = (long)plane * (H * W);
    const float* p = x + base;

    const int wl = (w0 == 0)     ? 1     : w0 - 1;
    const int wr = (w0 + 4 == W) ? W - 2 : w0 + 4;

    // reflected frame-row input indices (only f0 at h0==0, f5 at h0==H-4 reflect)
    const int hf0 = (h0 == 0) ? 1 : h0 - 1;
    const int hf5 = (h0 + 4 >= H) ? H - 2 : h0 + 4;

    // ---- phase A: rows f0..f3 ----
    Row6 f0 = load_row6(p + (long)hf0     * W, w0, wl, wr);
    Row6 f1 = load_row6(p + (long)h0      * W, w0, wl, wr);
    Row6 f2 = load_row6(p + (long)(h0 + 1) * W, w0, wl, wr);
    Row6 f3 = load_row6(p + (long)(h0 + 2) * W, w0, wl, wr);

    float pAl[6], pAh[6];
#pragma unroll
    for (int j = 0; j < 6; j++) {
        pAl[j] = fminf(f1.v[j], f2.v[j]);
        pAh[j] = fmaxf(f1.v[j], f2.v[j]);
    }
    // f1 dead from here (never a third)

    float* o = out + base + (long)h0 * W + w0;
    emit_row(pAl, pAh, f0, o);            // output row 0 ; f0 dies
    emit_row(pAl, pAh, f3, o + W);        // output row 1 ; pairA dies

    // ---- phase B: rows f4, f5 ----
    Row6 f4 = load_row6(p + (long)(h0 + 3) * W, w0, wl, wr);
    Row6 f5 = load_row6(p + (long)hf5      * W, w0, wl, wr);

    float pBl[6], pBh[6];
#pragma unroll
    for (int j = 0; j < 6; j++) {
        pBl[j] = fminf(f3.v[j], f4.v[j]);
        pBh[j] = fmaxf(f3.v[j], f4.v[j]);
    }
    // f3, f4 dead from here

    emit_row(pBl, pBh, f2, o + 2 * W);    // output row 2 ; f2 dies
    emit_row(pBl, pBh, f5, o + 3 * W);    // output row 3
}

extern "C" void kernel_launch(void* const* d_in, const int* in_sizes, int n_in,
                              void* d_out, int out_size) {
    const float* x = (const float*)d_in[0];
    float* out = (float*)d_out;
    dim3 grid(H / 4, 48);
    dim3 block(128);
    median3x3_kernel<<<grid, block>>>(x, out);
}